// round 1
// baseline (speedup 1.0000x reference)
#include <cuda_runtime.h>
#include <cuda_bf16.h>

#define N   512
#define B   32
#define NT  512            // one thread per column
#define NW  (NT / 32)      // 16 warps

// Per-batch matched-cost sums (doubles, deterministic two-stage reduction).
__device__ double g_batch_sums[B];

// ---------------------------------------------------------------------------
// One CTA per batch. Exact Jonker–Volgenant (e-maxx Hungarian) in double
// precision. State in SMEM; cost matrix rows streamed from L2.
// Column j in 1..N is owned by thread (j-1). Virtual column 0 by thread 0.
// ---------------------------------------------------------------------------
__global__ __launch_bounds__(NT, 1)
void lap_kernel(const float* __restrict__ D)
{
    const int b   = blockIdx.x;
    const float* __restrict__ C = D + (size_t)b * N * N;
    const int tid  = threadIdx.x;
    const int jc   = tid + 1;        // my column, 1-based
    const int lane = tid & 31;
    const int warp = tid >> 5;

    __shared__ double u[N + 1];
    __shared__ double v[N + 1];
    __shared__ double minv[N + 1];
    __shared__ int    p[N + 1];      // p[j] = row matched to col j (1-based), 0 = free
    __shared__ short  way[N + 1];
    __shared__ unsigned char used[N + 1];
    __shared__ unsigned long long red_key[NW];
    __shared__ int    s_j1;
    __shared__ double s_delta;

    // init duals / matching
    u[jc] = 0.0; v[jc] = 0.0; p[jc] = 0;
    if (tid == 0) { u[0] = 0.0; v[0] = 0.0; p[0] = 0; }
    __syncthreads();

    for (int i = 1; i <= N; ++i) {
        // per-row init
        minv[jc] = 1e300;
        used[jc] = 0;
        if (tid == 0) { p[0] = i; used[0] = 1; s_j1 = 0; }
        __syncthreads();

        int j0 = 0;
        while (true) {
            // mark j0 used (self-owned byte; j0==0 already marked)
            if (jc == j0) used[jc] = 1;

            const int    i0  = p[j0];
            const double ui0 = u[i0];

            unsigned long long key = ~0ull;
            if (!used[jc]) {
                double cur = (double)__ldg(&C[(size_t)(i0 - 1) * N + (jc - 1)])
                             - ui0 - v[jc];
                if (cur < minv[jc]) { minv[jc] = cur; way[jc] = (short)j0; }
                // nonneg doubles: bit pattern is order-isomorphic to u64.
                // Drop low 10 mantissa bits, stash column index there.
                key = (__double_as_longlong(minv[jc]) & ~0x3FFull)
                      | (unsigned long long)jc;
            }

            // warp-level min
            #pragma unroll
            for (int off = 16; off; off >>= 1) {
                unsigned long long o = __shfl_down_sync(0xffffffffu, key, off);
                key = (o < key) ? o : key;
            }
            if (lane == 0) red_key[warp] = key;
            __syncthreads();

            // cross-warp min (warp 0)
            if (warp == 0) {
                unsigned long long k = (lane < NW) ? red_key[lane] : ~0ull;
                #pragma unroll
                for (int off = 8; off; off >>= 1) {
                    unsigned long long o = __shfl_down_sync(0xffffffffu, k, off);
                    k = (o < k) ? o : k;
                }
                if (lane == 0) {
                    int j1 = (int)(k & 0x3FFull);
                    s_j1 = j1;
                    s_delta = minv[j1];   // exact delta, not the truncated key
                }
            }
            __syncthreads();

            const int    j1    = s_j1;
            const double delta = s_delta;

            // dual updates (parallel, disjoint targets)
            if (used[jc]) {
                u[p[jc]] += delta;
                v[jc]    -= delta;
            } else {
                double m = minv[jc] - delta;
                minv[jc] = (m > 0.0) ? m : 0.0;   // clamp ulp-negative from key truncation
            }
            if (tid == 0) { u[p[0]] += delta; v[0] -= delta; }

            j0 = j1;
            __syncthreads();                      // publish duals before next scan
            if (p[j1] == 0) break;                // reached a free column
        }

        // augment along alternating path (serial, thread 0; path in SMEM)
        if (tid == 0) {
            int j = s_j1;
            while (j) { int jp = way[j]; p[j] = p[jp]; j = jp; }
        }
        __syncthreads();
    }

    // matched-cost sum: col jc matched to row p[jc]
    double val = (double)__ldg(&C[(size_t)(p[jc] - 1) * N + (jc - 1)]);
    #pragma unroll
    for (int off = 16; off; off >>= 1)
        val += __shfl_down_sync(0xffffffffu, val, off);

    __shared__ double red_sum[NW];
    if (lane == 0) red_sum[warp] = val;
    __syncthreads();
    if (warp == 0) {
        double s = (lane < NW) ? red_sum[lane] : 0.0;
        #pragma unroll
        for (int off = 8; off; off >>= 1)
            s += __shfl_down_sync(0xffffffffu, s, off);
        if (lane == 0) g_batch_sums[b] = s;
    }
}

// deterministic final reduction over batches
__global__ void finalize_kernel(float* __restrict__ out)
{
    const int lane = threadIdx.x;
    double s = (lane < B) ? g_batch_sums[lane] : 0.0;
    #pragma unroll
    for (int off = 16; off; off >>= 1)
        s += __shfl_down_sync(0xffffffffu, s, off);
    if (lane == 0) out[0] = (float)(s / (double)(B * N));
}

extern "C" void kernel_launch(void* const* d_in, const int* in_sizes, int n_in,
                              void* d_out, int out_size)
{
    const float* D = (const float*)d_in[0];
    lap_kernel<<<B, NT>>>(D);
    finalize_kernel<<<1, 32>>>((float*)d_out);
}

// round 2
// speedup vs baseline: 6.6779x; 6.6779x over previous
#include <cuda_runtime.h>

#define N     512
#define B     32
#define NF4   (N / 4)         // float4 per row
#define ROOTW 0xFFFF

__device__ double g_batch_sums[B];

// col owned by (lane, k):  j = (k>>2)*128 + lane*4 + (k&3)   (coalesced float4 loads)
#define JCOL(k) ((((k) >> 2) << 7) + (lane << 2) + ((k) & 3))

#define LOADROW(ptr)                                                         \
    do {                                                                     \
        const float4* _r = (ptr);                                            \
        float4 _t0 = _r[lane];      float4 _t1 = _r[lane + 32];              \
        float4 _t2 = _r[lane + 64]; float4 _t3 = _r[lane + 96];              \
        c[0]=_t0.x; c[1]=_t0.y; c[2]=_t0.z; c[3]=_t0.w;                      \
        c[4]=_t1.x; c[5]=_t1.y; c[6]=_t1.z; c[7]=_t1.w;                      \
        c[8]=_t2.x; c[9]=_t2.y; c[10]=_t2.z; c[11]=_t2.w;                    \
        c[12]=_t3.x; c[13]=_t3.y; c[14]=_t3.z; c[15]=_t3.w;                  \
    } while (0)

__global__ __launch_bounds__(32, 1)
void lap_kernel(const float* __restrict__ D)
{
    const int b    = blockIdx.x;
    const int lane = threadIdx.x;
    const float*  __restrict__ C  = D + (size_t)b * N * N;
    const float4* __restrict__ C4 = (const float4*)C;

    __shared__ float          u[N];      // row duals
    __shared__ int            prow[N];   // row matched to col j (-1 = free)
    __shared__ unsigned short way[N];    // predecessor column on shortest path
    __shared__ float          dpop[N];   // dist at pop time

    for (int k = lane; k < N; k += 32) { u[k] = 0.f; prow[k] = -1; }

    float v[16];                          // column duals (owned)
#pragma unroll
    for (int k = 0; k < 16; ++k) v[k] = 0.f;
    __syncwarp();

    const float INF = __uint_as_float(0x7F800000u);

    float c[16];
    LOADROW(C4);                          // prefetch row 0

    for (int i = 0; i < N; ++i) {
        // cv = C[i0][j] - v[j] for current row; uinf = 0 (live) / INF (used)
        float cv[16], uinf[16];
        unsigned key[16];
#pragma unroll
        for (int k = 0; k < 16; ++k) {
            cv[k]   = c[k] - v[k];
            uinf[k] = 0.f;
            key[k]  = 0xFFFFFFFFu;
        }

        float          base = -u[i];      // dist(root)=0, i0 = i
        unsigned short j0s  = ROOTW;
        int   jfree;
        float dfinal;

        while (true) {
            // ---- relax my 16 columns against row i0 ----
#pragma unroll
            for (int k = 0; k < 16; ++k) {
                float cur   = fmaxf(base + cv[k], uinf[k]);   // clamp>=0 AND used->INF
                unsigned pc = ((__float_as_uint(cur) + 0x200u) & ~0x3FFu)
                              | (unsigned)JCOL(k);
                if (pc < key[k]) { key[k] = pc; way[JCOL(k)] = j0s; }
            }
            // ---- global argmin: local tree + one REDUX ----
            unsigned m = key[0];
#pragma unroll
            for (int k = 1; k < 16; ++k) m = min(m, key[k]);
            unsigned gmin = __reduce_min_sync(0xffffffffu, m);
            const int   j1 = (int)(gmin & 0x3FFu);
            const float dl = __uint_as_float(gmin & ~0x3FFu);

            const int i1 = prow[j1];
            if (i1 < 0) { jfree = j1; dfinal = dl; break; }   // reached a free column

            if (lane == 0) dpop[j1] = dl;
            // mark j1 used: only the owner's key equals gmin (index in low bits)
#pragma unroll
            for (int k = 0; k < 16; ++k)
                if (key[k] == gmin) {
                    uinf[k] = INF;
                    key[k]  = 0x7F800000u | (unsigned)JCOL(k); // never wins, never rewrites way
                }

            // prefetch next row ASAP, overlap with bookkeeping
            LOADROW(C4 + (size_t)i1 * NF4);
            base = dl - u[i1];
            j0s  = (unsigned short)j1;
#pragma unroll
            for (int k = 0; k < 16; ++k) cv[k] = c[k] - v[k];
        }

        __syncwarp();

        // prefetch first row of next augmentation before the serial tail
        if (i + 1 < N) LOADROW(C4 + (size_t)(i + 1) * NF4);

        // ---- one-shot dual updates (Dijkstra-with-potentials) ----
#pragma unroll
        for (int k = 0; k < 16; ++k) {
            if (uinf[k] > 0.f) {                       // col was popped
                int   j   = JCOL(k);
                float adj = dfinal - dpop[j];
                v[k]     -= adj;
                u[prow[j]] += adj;                     // distinct rows: race-free
            }
        }
        if (lane == 0) u[i] += dfinal;
        __syncwarp();

        // ---- augment along the alternating path (serial, lane 0) ----
        if (lane == 0) {
            int j = jfree;
            while (true) {
                int jp = way[j];
                if (jp == ROOTW) { prow[j] = i; break; }
                prow[j] = prow[jp];
                j = jp;
            }
        }
        __syncwarp();
    }

    // ---- matched-cost sum (double, deterministic) ----
    double s = 0.0;
#pragma unroll
    for (int k = 0; k < 16; ++k) {
        int j = JCOL(k);
        s += (double)__ldg(&C[(size_t)prow[j] * N + j]);
    }
#pragma unroll
    for (int off = 16; off; off >>= 1)
        s += __shfl_down_sync(0xffffffffu, s, off);
    if (lane == 0) g_batch_sums[b] = s;
}

__global__ void finalize_kernel(float* __restrict__ out)
{
    const int lane = threadIdx.x;
    double s = (lane < B) ? g_batch_sums[lane] : 0.0;
#pragma unroll
    for (int off = 16; off; off >>= 1)
        s += __shfl_down_sync(0xffffffffu, s, off);
    if (lane == 0) out[0] = (float)(s / (double)(B * N));
}

extern "C" void kernel_launch(void* const* d_in, const int* in_sizes, int n_in,
                              void* d_out, int out_size)
{
    const float* D = (const float*)d_in[0];
    lap_kernel<<<B, 32>>>(D);
    finalize_kernel<<<1, 32>>>((float*)d_out);
}

// round 3
// speedup vs baseline: 8.6481x; 1.2950x over previous
#include <cuda_runtime.h>

#define N     512
#define B     32
#define NF4   (N / 4)
#define ROOTW 0xFFFF

__device__ double g_batch_sums[B];

// col owned by (lane, k):  j = (k>>2)*128 + lane*4 + (k&3)   (coalesced float4)
#define JCOL(k) ((((k) >> 2) << 7) + (lane << 2) + ((k) & 3))

#define LOADROW(dst, ptr)                                                    \
    do {                                                                     \
        const float4* _r = (ptr);                                            \
        float4 _t0 = _r[lane];      float4 _t1 = _r[lane + 32];              \
        float4 _t2 = _r[lane + 64]; float4 _t3 = _r[lane + 96];              \
        dst[0]=_t0.x;  dst[1]=_t0.y;  dst[2]=_t0.z;  dst[3]=_t0.w;           \
        dst[4]=_t1.x;  dst[5]=_t1.y;  dst[6]=_t1.z;  dst[7]=_t1.w;           \
        dst[8]=_t2.x;  dst[9]=_t2.y;  dst[10]=_t2.z; dst[11]=_t2.w;          \
        dst[12]=_t3.x; dst[13]=_t3.y; dst[14]=_t3.z; dst[15]=_t3.w;          \
    } while (0)

__global__ __launch_bounds__(32, 1)
void lap_kernel(const float* __restrict__ D)
{
    const int b    = blockIdx.x;
    const int lane = threadIdx.x;
    const float*  __restrict__ C  = D + (size_t)b * N * N;
    const float4* __restrict__ C4 = (const float4*)C;

    __shared__ float          u[N];       // row duals
    __shared__ int            prow[N];    // row matched to col j (-1 = free)
    __shared__ unsigned short way[N];     // predecessor col on shortest path
    __shared__ float          dpop[N];    // dist at pop time
    __shared__ short          aminS[N];   // argmin row per column (CR)
    __shared__ unsigned char  rowUsed[N];
    __shared__ short          flist[N];   // free rows after greedy
    __shared__ int            s_nfree;

    for (int k = lane; k < N; k += 32) { u[k] = 0.f; prow[k] = -1; rowUsed[k] = 0; }

    const float INF = __uint_as_float(0x7F800000u);

    // ================= column reduction: v[j] = min_i C[i][j] ==============
    float v[16];
    short amin[16];
#pragma unroll
    for (int k = 0; k < 16; ++k) { v[k] = INF; amin[k] = 0; }

    float c[16], c2[16];
    for (int r = 0; r < N; r += 2) {
        LOADROW(c,  C4 + (size_t)r * NF4);
        LOADROW(c2, C4 + (size_t)(r + 1) * NF4);
#pragma unroll
        for (int k = 0; k < 16; ++k)
            if (c[k]  < v[k]) { v[k] = c[k];  amin[k] = (short)r; }
#pragma unroll
        for (int k = 0; k < 16; ++k)
            if (c2[k] < v[k]) { v[k] = c2[k]; amin[k] = (short)(r + 1); }
    }
#pragma unroll
    for (int k = 0; k < 16; ++k) aminS[JCOL(k)] = amin[k];
    __syncwarp();

    // ================= greedy assignment + free-row list (lane 0) ==========
    if (lane == 0) {
        for (int j = 0; j < N; ++j) {
            int i = aminS[j];
            if (!rowUsed[i]) { rowUsed[i] = 1; prow[j] = i; }
        }
        int nf = 0;
        for (int i = 0; i < N; ++i)
            if (!rowUsed[i]) flist[nf++] = (short)i;
        s_nfree = nf;
    }
    __syncwarp();
    const int nfree = s_nfree;

    // ================= shortest augmenting paths for free rows =============
    if (nfree > 0) {
        LOADROW(c, C4 + (size_t)flist[0] * NF4);   // prefetch first root row

        for (int idx = 0; idx < nfree; ++idx) {
            const int i = flist[idx];

            float    uinf[16];
            unsigned key[16];
#pragma unroll
            for (int k = 0; k < 16; ++k) { uinf[k] = 0.f; key[k] = 0xFFFFFFFFu; }

            float          base = -u[i];
            unsigned short j0s  = ROOTW;
            int   jfree;
            float dfinal;

            while (true) {
                // ---- relax my 16 columns against row i0 ----
#pragma unroll
                for (int k = 0; k < 16; ++k) {
                    float cur   = fmaxf((c[k] - v[k]) + base, uinf[k]);
                    unsigned pc = ((__float_as_uint(cur) + 0x200u) & ~0x3FFu)
                                  | (unsigned)JCOL(k);
                    if (pc < key[k]) { key[k] = pc; way[JCOL(k)] = j0s; }
                }
                // ---- argmin: local tree + one REDUX ----
                unsigned m = key[0];
#pragma unroll
                for (int k = 1; k < 16; ++k) m = min(m, key[k]);
                unsigned gmin = __reduce_min_sync(0xffffffffu, m);
                const int   j1 = (int)(gmin & 0x3FFu);
                const float dl = __uint_as_float(gmin & ~0x3FFu);

                const int i1 = prow[j1];
                if (i1 < 0) { jfree = j1; dfinal = dl; break; }

                if (lane == 0) dpop[j1] = dl;
#pragma unroll
                for (int k = 0; k < 16; ++k)
                    if (key[k] == gmin) {
                        uinf[k] = INF;
                        key[k]  = 0x7F800000u | (unsigned)JCOL(k);
                    }

                LOADROW(c, C4 + (size_t)i1 * NF4);   // demand row, overlap rest
                base = dl - u[i1];
                j0s  = (unsigned short)j1;
            }

            __syncwarp();

            // prefetch next root row before serial tail
            if (idx + 1 < nfree) LOADROW(c, C4 + (size_t)flist[idx + 1] * NF4);

            // ---- one-shot dual updates ----
#pragma unroll
            for (int k = 0; k < 16; ++k) {
                if (uinf[k] > 0.f) {                  // col was popped
                    int   j   = JCOL(k);
                    float adj = dfinal - dpop[j];
                    v[k]       -= adj;
                    u[prow[j]] += adj;                // distinct rows: race-free
                }
            }
            if (lane == 0) u[i] += dfinal;
            __syncwarp();

            // ---- augment along alternating path (serial, lane 0) ----
            if (lane == 0) {
                int j = jfree;
                while (true) {
                    int jp = way[j];
                    if (jp == ROOTW) { prow[j] = i; break; }
                    prow[j] = prow[jp];
                    j = jp;
                }
            }
            __syncwarp();
        }
    }

    // ---- matched-cost sum (double, deterministic) ----
    double s = 0.0;
#pragma unroll
    for (int k = 0; k < 16; ++k) {
        int j = JCOL(k);
        s += (double)__ldg(&C[(size_t)prow[j] * N + j]);
    }
#pragma unroll
    for (int off = 16; off; off >>= 1)
        s += __shfl_down_sync(0xffffffffu, s, off);
    if (lane == 0) g_batch_sums[b] = s;
}

__global__ void finalize_kernel(float* __restrict__ out)
{
    const int lane = threadIdx.x;
    double s = (lane < B) ? g_batch_sums[lane] : 0.0;
#pragma unroll
    for (int off = 16; off; off >>= 1)
        s += __shfl_down_sync(0xffffffffu, s, off);
    if (lane == 0) out[0] = (float)(s / (double)(B * N));
}

extern "C" void kernel_launch(void* const* d_in, const int* in_sizes, int n_in,
                              void* d_out, int out_size)
{
    const float* D = (const float*)d_in[0];
    lap_kernel<<<B, 32>>>(D);
    finalize_kernel<<<1, 32>>>((float*)d_out);
}

// round 4
// speedup vs baseline: 9.1662x; 1.0599x over previous
#include <cuda_runtime.h>

#define N     512
#define B     32
#define NF4   (N / 4)
#define ROOTW 0xFFFF

__device__ double g_batch_sums[B];

// col owned by (lane, k):  j = (k>>2)*128 + lane*4 + (k&3)   (coalesced float4)
#define JCOL(k) ((((k) >> 2) << 7) + (lane << 2) + ((k) & 3))

#define LOADROW(dst, ptr)                                                    \
    do {                                                                     \
        const float4* _r = (ptr);                                            \
        float4 _t0 = _r[lane];      float4 _t1 = _r[lane + 32];              \
        float4 _t2 = _r[lane + 64]; float4 _t3 = _r[lane + 96];              \
        dst[0]=_t0.x;  dst[1]=_t0.y;  dst[2]=_t0.z;  dst[3]=_t0.w;           \
        dst[4]=_t1.x;  dst[5]=_t1.y;  dst[6]=_t1.z;  dst[7]=_t1.w;           \
        dst[8]=_t2.x;  dst[9]=_t2.y;  dst[10]=_t2.z; dst[11]=_t2.w;          \
        dst[12]=_t3.x; dst[13]=_t3.y; dst[14]=_t3.z; dst[15]=_t3.w;          \
    } while (0)

__global__ __launch_bounds__(32, 1)
void lap_kernel(const float* __restrict__ D)
{
    const int b    = blockIdx.x;
    const int lane = threadIdx.x;
    const float*  __restrict__ C  = D + (size_t)b * N * N;
    const float4* __restrict__ C4 = (const float4*)C;

    __shared__ float          u[N];        // row duals
    __shared__ int            prow[N];     // row matched to col j (-1 = free)
    __shared__ unsigned short way[N];      // predecessor col on shortest path
    __shared__ float          dpop[N];     // dist at pop time
    __shared__ short          aminS[N];    // argmin row per column (CR)
    __shared__ unsigned char  rowUsed[N];
    __shared__ short          flist[3 * N];// free-row queue (ARR can push)
    __shared__ int            s_nfree;
    __shared__ float          s_u1, s_u2;

    for (int k = lane; k < N; k += 32) { u[k] = 0.f; prow[k] = -1; rowUsed[k] = 0; }

    const float INF = __uint_as_float(0x7F800000u);

    // ================= column reduction: v[j] = min_i C[i][j] ==============
    float v[16];
    short amin[16];
#pragma unroll
    for (int k = 0; k < 16; ++k) { v[k] = INF; amin[k] = 0; }

    float c[16], cS[16];
    for (int r = 0; r < N; r += 2) {
        LOADROW(c,  C4 + (size_t)r * NF4);
        LOADROW(cS, C4 + (size_t)(r + 1) * NF4);
#pragma unroll
        for (int k = 0; k < 16; ++k)
            if (c[k]  < v[k]) { v[k] = c[k];  amin[k] = (short)r; }
#pragma unroll
        for (int k = 0; k < 16; ++k)
            if (cS[k] < v[k]) { v[k] = cS[k]; amin[k] = (short)(r + 1); }
    }
#pragma unroll
    for (int k = 0; k < 16; ++k) aminS[JCOL(k)] = amin[k];
    __syncwarp();

    // ================= greedy assignment + free-row queue (lane 0) =========
    if (lane == 0) {
        for (int j = 0; j < N; ++j) {
            int i = aminS[j];
            if (!rowUsed[i]) { rowUsed[i] = 1; prow[j] = i; }
        }
        int nf = 0;
        for (int i = 0; i < N; ++i)
            if (!rowUsed[i]) flist[nf++] = (short)i;
        s_nfree = nf;
    }
    __syncwarp();

    int head = 0, tail = s_nfree;
    const int lim = 2 * tail;
    int cnt = 0;

    // ================= augmenting row reduction (bounded JV ARR) ===========
    if (head < tail) LOADROW(c, C4 + (size_t)flist[0] * NF4);
    while (head < tail && cnt < lim) {
        const int i = flist[head]; ++head; ++cnt;

        float r[16]; unsigned kk[16];
#pragma unroll
        for (int k = 0; k < 16; ++k) {
            r[k]  = c[k] - v[k];
            kk[k] = ((__float_as_uint(r[k]) + 0x200u) & ~0x3FFu) | (unsigned)JCOL(k);
        }
        unsigned m = kk[0];
#pragma unroll
        for (int k = 1; k < 16; ++k) m = min(m, kk[k]);
        const unsigned g1 = __reduce_min_sync(0xffffffffu, m);
        const int j1 = (int)(g1 & 0x3FFu);

        unsigned m2 = 0xFFFFFFFFu;
#pragma unroll
        for (int k = 0; k < 16; ++k) m2 = min(m2, (kk[k] == g1) ? 0xFFFFFFFFu : kk[k]);
        const unsigned g2 = __reduce_min_sync(0xffffffffu, m2);
        const int j2 = (int)(g2 & 0x3FFu);

        // exact values from owner lanes
#pragma unroll
        for (int k = 0; k < 16; ++k) if (JCOL(k) == j1) s_u1 = r[k];
#pragma unroll
        for (int k = 0; k < 16; ++k) if (JCOL(k) == j2) s_u2 = r[k];
        __syncwarp();
        const float u1 = s_u1, u2 = s_u2;

        int jsel = j1;
        if (u1 < u2) {
#pragma unroll
            for (int k = 0; k < 16; ++k) if (JCOL(k) == j1) v[k] -= (u2 - u1);
        } else if (prow[j1] >= 0) {
            jsel = j2;
        }
        const int iold = prow[jsel];
        if (lane == 0) {
            prow[jsel] = i;
            u[i] = u2;
            if (iold >= 0) flist[tail] = (short)iold;
        }
        if (iold >= 0) ++tail;
        __syncwarp();
        if (head < tail && cnt < lim)
            LOADROW(c, C4 + (size_t)flist[head] * NF4);
    }

    // ================= shortest augmenting paths for remaining rows ========
    if (head < tail) LOADROW(c, C4 + (size_t)flist[head] * NF4);

    for (int idx = head; idx < tail; ++idx) {
        const int i = flist[idx];

        float    uinf[16];
        unsigned key[16];
#pragma unroll
        for (int k = 0; k < 16; ++k) { uinf[k] = 0.f; key[k] = 0xFFFFFFFFu; }

        float          base = -u[i];
        unsigned short j0s  = ROOTW;
        int   jpred = -1;
        int   jfreeC;
        float dfinal;

        while (true) {
            // ---- relax my 16 columns against current row ----
#pragma unroll
            for (int k = 0; k < 16; ++k) {
                float cur   = fmaxf((c[k] - v[k]) + base, uinf[k]);
                unsigned pc = ((__float_as_uint(cur) + 0x200u) & ~0x3FFu)
                              | (unsigned)JCOL(k);
                if (pc < key[k]) { key[k] = pc; way[JCOL(k)] = j0s; }
            }
            unsigned m = key[0];
#pragma unroll
            for (int k = 1; k < 16; ++k) m = min(m, key[k]);
            const unsigned gmin = __reduce_min_sync(0xffffffffu, m);
            const int   j1 = (int)(gmin & 0x3FFu);
            const float dl = __uint_as_float(gmin & ~0x3FFu);

            const int i1 = prow[j1];
            if (i1 < 0) { jfreeC = j1; dfinal = dl; break; }

            if (lane == 0) dpop[j1] = dl;
            // mark popped col used + poison its key
#pragma unroll
            for (int k = 0; k < 16; ++k)
                if (key[k] == gmin) {
                    uinf[k] = INF;
                    key[k]  = 0x7F800000u | (unsigned)JCOL(k);
                }

            const bool hit = (j1 == jpred);       // warp-uniform
            if (hit) {
#pragma unroll
                for (int k = 0; k < 16; ++k) c[k] = cS[k];   // speculated row
            } else {
                LOADROW(c, C4 + (size_t)i1 * NF4);           // demand row
            }

            // ---- runner-up prediction for the NEXT pop ----
            unsigned m2 = key[0];
#pragma unroll
            for (int k = 1; k < 16; ++k) m2 = min(m2, key[k]);
            const unsigned g2p = __reduce_min_sync(0xffffffffu, m2);
            const int jp = (int)(g2p & 0x3FFu);
            const int ip = prow[jp];
            if (ip >= 0) { LOADROW(cS, C4 + (size_t)ip * NF4); jpred = jp; }
            else         { jpred = -1; }

            base = dl - u[i1];
            j0s  = (unsigned short)j1;
        }

        __syncwarp();

        // prefetch next root row before the serial tail
        if (idx + 1 < tail) LOADROW(c, C4 + (size_t)flist[idx + 1] * NF4);

        // ---- one-shot dual updates (Dijkstra-with-potentials) ----
#pragma unroll
        for (int k = 0; k < 16; ++k) {
            if (uinf[k] > 0.f) {                   // col was popped
                int   j   = JCOL(k);
                float adj = dfinal - dpop[j];
                v[k]       -= adj;
                u[prow[j]] += adj;                 // distinct rows: race-free
            }
        }
        if (lane == 0) u[i] += dfinal;
        __syncwarp();

        // ---- augment along alternating path (serial, lane 0) ----
        if (lane == 0) {
            int j = jfreeC;
            while (true) {
                int jpth = way[j];
                if (jpth == ROOTW) { prow[j] = i; break; }
                prow[j] = prow[jpth];
                j = jpth;
            }
        }
        __syncwarp();
    }

    // ---- matched-cost sum (double, deterministic) ----
    double s = 0.0;
#pragma unroll
    for (int k = 0; k < 16; ++k) {
        int j = JCOL(k);
        s += (double)__ldg(&C[(size_t)prow[j] * N + j]);
    }
#pragma unroll
    for (int off = 16; off; off >>= 1)
        s += __shfl_down_sync(0xffffffffu, s, off);
    if (lane == 0) g_batch_sums[b] = s;
}

__global__ void finalize_kernel(float* __restrict__ out)
{
    const int lane = threadIdx.x;
    double s = (lane < B) ? g_batch_sums[lane] : 0.0;
#pragma unroll
    for (int off = 16; off; off >>= 1)
        s += __shfl_down_sync(0xffffffffu, s, off);
    if (lane == 0) out[0] = (float)(s / (double)(B * N));
}

extern "C" void kernel_launch(void* const* d_in, const int* in_sizes, int n_in,
                              void* d_out, int out_size)
{
    const float* D = (const float*)d_in[0];
    lap_kernel<<<B, 32>>>(D);
    finalize_kernel<<<1, 32>>>((float*)d_out);
}

// round 5
// speedup vs baseline: 12.7308x; 1.3889x over previous
#include <cuda_runtime.h>

#define N     512
#define B     32
#define NF4   (N / 4)
#define NT    128
#define NWP   4
#define ROOTW 0xFFFF

__device__ double g_batch_sums[B];

// thread owns cols [4*tid, 4*tid+4); one float4 per thread per row (coalesced)
#define LOADROW(dst, row)                                                    \
    do {                                                                     \
        float4 _t = C4[(size_t)(row) * NF4 + tid];                           \
        dst[0] = _t.x; dst[1] = _t.y; dst[2] = _t.z; dst[3] = _t.w;          \
    } while (0)

__global__ __launch_bounds__(NT, 1)
void lap_kernel(const float* __restrict__ D)
{
    const int b    = blockIdx.x;
    const int tid  = threadIdx.x;
    const int lane = tid & 31;
    const int wrp  = tid >> 5;
    const int jc0  = tid << 2;                 // first owned column
    const float*  __restrict__ C  = D + (size_t)b * N * N;
    const float4* __restrict__ C4 = (const float4*)C;

    __shared__ float          u[N];
    __shared__ int            prow[N];
    __shared__ unsigned short way[N];
    __shared__ float          dpop[N];
    __shared__ short          aminS[N];
    __shared__ unsigned char  rowUsed[N];
    __shared__ short          flist[3 * N];
    __shared__ int            s_nfree, s_iold;
    __shared__ unsigned       red1[2][NWP], red2[2][NWP];
    __shared__ double         red_s[NWP];

    for (int k = tid; k < N; k += NT) { u[k] = 0.f; prow[k] = -1; rowUsed[k] = 0; }

    const float INF = __uint_as_float(0x7F800000u);

    // ================= column reduction: v[j] = min_i C[i][j] ==============
    float v[4]; short amin[4];
#pragma unroll
    for (int k = 0; k < 4; ++k) { v[k] = INF; amin[k] = 0; }

    float c[4], cS[4];
    for (int r = 0; r < N; r += 2) {
        float4 t0 = C4[(size_t)r * NF4 + tid];
        float4 t1 = C4[(size_t)(r + 1) * NF4 + tid];
        float a0[4] = {t0.x, t0.y, t0.z, t0.w};
        float a1[4] = {t1.x, t1.y, t1.z, t1.w};
#pragma unroll
        for (int k = 0; k < 4; ++k)
            if (a0[k] < v[k]) { v[k] = a0[k]; amin[k] = (short)r; }
#pragma unroll
        for (int k = 0; k < 4; ++k)
            if (a1[k] < v[k]) { v[k] = a1[k]; amin[k] = (short)(r + 1); }
    }
#pragma unroll
    for (int k = 0; k < 4; ++k) aminS[jc0 + k] = amin[k];
    __syncthreads();

    // ================= greedy assignment + free-row queue (tid 0) ==========
    if (tid == 0) {
        for (int j = 0; j < N; ++j) {
            int i = aminS[j];
            if (!rowUsed[i]) { rowUsed[i] = 1; prow[j] = i; }
        }
        int nf = 0;
        for (int i = 0; i < N; ++i)
            if (!rowUsed[i]) flist[nf++] = (short)i;
        s_nfree = nf;
    }
    __syncthreads();

    int head = 0, tail = s_nfree;
    const int lim = 2 * tail;
    int cnt = 0, pp = 0;

    // ================= augmenting row reduction (bounded JV ARR) ===========
    if (head < tail) LOADROW(c, flist[0]);
    while (head < tail && cnt < lim) {
        const int i = flist[head]; ++head; ++cnt;

        unsigned kk[4];
#pragma unroll
        for (int k = 0; k < 4; ++k) {
            float r0 = c[k] - v[k];
            kk[k] = ((__float_as_uint(r0) + 0x200u) & ~0x3FFu) | (unsigned)(jc0 + k);
        }
        unsigned m = min(min(kk[0], kk[1]), min(kk[2], kk[3]));
        m = __reduce_min_sync(0xffffffffu, m);
        if (lane == 0) red1[pp][wrp] = m;

        unsigned m2 = 0xFFFFFFFFu;                 // prepared before bar; poisoned after
        __syncthreads();                                            // bar 1
        const unsigned g1 = min(min(red1[pp][0], red1[pp][1]),
                                min(red1[pp][2], red1[pp][3]));
        const int j1 = (int)(g1 & 0x3FFu);

#pragma unroll
        for (int k = 0; k < 4; ++k) m2 = min(m2, (kk[k] == g1) ? 0xFFFFFFFFu : kk[k]);
        m2 = __reduce_min_sync(0xffffffffu, m2);
        if (lane == 0) red2[pp][wrp] = m2;
        __syncthreads();                                            // bar 2
        const unsigned g2 = min(min(red2[pp][0], red2[pp][1]),
                                min(red2[pp][2], red2[pp][3]));
        const int j2 = (int)(g2 & 0x3FFu);
        const float u1 = __uint_as_float(g1 & ~0x3FFu);
        const float u2 = __uint_as_float(g2 & ~0x3FFu);

        int jsel = j1;
        if (u1 < u2) {
            if ((unsigned)(j1 - jc0) < 4u) v[j1 - jc0] -= (u2 - u1);
        } else if (prow[j1] >= 0) {
            jsel = j2;
        }
        if (tid == 0) {
            int iold = prow[jsel];
            prow[jsel] = i;
            u[i] = u2;
            if (iold >= 0) flist[tail] = (short)iold;
            s_iold = iold;
        }
        pp ^= 1;
        __syncthreads();                                            // bar 3
        if (s_iold >= 0) ++tail;
        if (head < tail && cnt < lim) LOADROW(c, flist[head]);
    }

    // ================= shortest augmenting paths ===========================
    if (head < tail) LOADROW(c, flist[head]);

    for (int idx = head; idx < tail; ++idx) {
        const int i = flist[idx];

        float    uinf[4];
        unsigned key[4];
#pragma unroll
        for (int k = 0; k < 4; ++k) { uinf[k] = 0.f; key[k] = 0xFFFFFFFFu; }

        float          base = -u[i];
        unsigned short j0s  = ROOTW;
        int   jpred = -1;
        int   jfreeC;
        float dfinal;

        while (true) {
            // ---- relax my 4 columns ----
#pragma unroll
            for (int k = 0; k < 4; ++k) {
                float cur   = fmaxf((c[k] - v[k]) + base, uinf[k]);
                unsigned pc = ((__float_as_uint(cur) + 0x200u) & ~0x3FFu)
                              | (unsigned)(jc0 + k);
                if (pc < key[k]) { key[k] = pc; way[jc0 + k] = j0s; }
            }
            unsigned m = min(min(key[0], key[1]), min(key[2], key[3]));
            m = __reduce_min_sync(0xffffffffu, m);
            if (lane == 0) red1[pp][wrp] = m;
            __syncthreads();                                        // bar A
            const unsigned gmin = min(min(red1[pp][0], red1[pp][1]),
                                      min(red1[pp][2], red1[pp][3]));
            const int   j1 = (int)(gmin & 0x3FFu);
            const float dl = __uint_as_float(gmin & ~0x3FFu);

            const int i1 = prow[j1];
            if (i1 < 0) { jfreeC = j1; dfinal = dl; pp ^= 1; break; }

            if (tid == 0) dpop[j1] = dl;
#pragma unroll
            for (int k = 0; k < 4; ++k)
                if (key[k] == gmin) {
                    uinf[k] = INF;
                    key[k]  = 0x7F800000u | (unsigned)(jc0 + k);
                }

            const bool hit = (j1 == jpred);       // uniform
            if (hit) {
#pragma unroll
                for (int k = 0; k < 4; ++k) c[k] = cS[k];
            } else {
                LOADROW(c, i1);                    // demand row
            }

            // ---- runner-up prediction (in the load shadow) ----
            unsigned m2 = min(min(key[0], key[1]), min(key[2], key[3]));
            m2 = __reduce_min_sync(0xffffffffu, m2);
            if (lane == 0) red2[pp][wrp] = m2;
            __syncthreads();                                        // bar B
            const unsigned g2 = min(min(red2[pp][0], red2[pp][1]),
                                    min(red2[pp][2], red2[pp][3]));
            const int jp = (int)(g2 & 0x3FFu);
            const int ip = prow[jp];
            if (ip >= 0) { LOADROW(cS, ip); jpred = jp; }
            else         { jpred = -1; }

            base = dl - u[i1];
            j0s  = (unsigned short)j1;
            pp  ^= 1;
        }

        __syncthreads();              // dpop visible; all past break

        // prefetch next root row before serial tail
        if (idx + 1 < tail) LOADROW(c, flist[idx + 1]);

        // ---- one-shot dual updates ----
#pragma unroll
        for (int k = 0; k < 4; ++k) {
            if (uinf[k] > 0.f) {                  // col was popped
                int   j   = jc0 + k;
                float adj = dfinal - dpop[j];
                v[k]       -= adj;
                u[prow[j]] += adj;                // distinct rows: race-free
            }
        }
        if (tid == 0) u[i] += dfinal;
        __syncthreads();

        // ---- augment along alternating path (serial, tid 0) ----
        if (tid == 0) {
            int j = jfreeC;
            while (true) {
                int jpth = way[j];
                if (jpth == ROOTW) { prow[j] = i; break; }
                prow[j] = prow[jpth];
                j = jpth;
            }
        }
        __syncthreads();
    }

    // ---- matched-cost sum (double, deterministic order) ----
    double s = 0.0;
#pragma unroll
    for (int k = 0; k < 4; ++k) {
        int j = jc0 + k;
        s += (double)__ldg(&C[(size_t)prow[j] * N + j]);
    }
#pragma unroll
    for (int off = 16; off; off >>= 1)
        s += __shfl_down_sync(0xffffffffu, s, off);
    if (lane == 0) red_s[wrp] = s;
    __syncthreads();
    if (tid == 0)
        g_batch_sums[b] = ((red_s[0] + red_s[1]) + (red_s[2] + red_s[3]));
}

__global__ void finalize_kernel(float* __restrict__ out)
{
    const int lane = threadIdx.x;
    double s = (lane < B) ? g_batch_sums[lane] : 0.0;
#pragma unroll
    for (int off = 16; off; off >>= 1)
        s += __shfl_down_sync(0xffffffffu, s, off);
    if (lane == 0) out[0] = (float)(s / (double)(B * N));
}

extern "C" void kernel_launch(void* const* d_in, const int* in_sizes, int n_in,
                              void* d_out, int out_size)
{
    const float* D = (const float*)d_in[0];
    lap_kernel<<<B, NT>>>(D);
    finalize_kernel<<<1, 32>>>((float*)d_out);
}

// round 6
// speedup vs baseline: 13.1726x; 1.0347x over previous
#include <cuda_runtime.h>

#define N     512
#define B     32
#define NF4   (N / 4)
#define NT    128
#define NWP   4
#define ROOTW 0xFFFF

__device__ double g_batch_sums[B];

// thread owns cols [4*tid, 4*tid+4); one float4 per thread per row (coalesced)
#define LOADROW(dst, row)                                                    \
    do {                                                                     \
        float4 _t = C4[(size_t)(row) * NF4 + tid];                           \
        dst[0] = _t.x; dst[1] = _t.y; dst[2] = _t.z; dst[3] = _t.w;          \
    } while (0)

__global__ __launch_bounds__(NT, 1)
void lap_kernel(const float* __restrict__ D)
{
    const int b    = blockIdx.x;
    const int tid  = threadIdx.x;
    const int lane = tid & 31;
    const int wrp  = tid >> 5;
    const int jc0  = tid << 2;
    const float*  __restrict__ C  = D + (size_t)b * N * N;
    const float4* __restrict__ C4 = (const float4*)C;

    __shared__ float          u[N];
    __shared__ int            prow[N];
    __shared__ unsigned short way[N];
    __shared__ float          dpop[N];
    __shared__ short          aminS[N];
    __shared__ unsigned char  rowUsed[N];
    __shared__ short          flist[3 * N];
    __shared__ short          alist[N];
    __shared__ int            s_nfree, s_iold, s_na;
    __shared__ unsigned       red1[2][NWP], red2[2][NWP];
    __shared__ double         red_s[NWP];

    for (int k = tid; k < N; k += NT) { u[k] = 0.f; prow[k] = -1; rowUsed[k] = 0; }

    const float INF = __uint_as_float(0x7F800000u);

    // ================= column reduction: v[j] = min_i C[i][j] ==============
    float v[4]; short amin[4];
#pragma unroll
    for (int k = 0; k < 4; ++k) { v[k] = INF; amin[k] = 0; }

    float c[4], cS[4], cT[4];
    for (int r = 0; r < N; r += 2) {
        float4 t0 = C4[(size_t)r * NF4 + tid];
        float4 t1 = C4[(size_t)(r + 1) * NF4 + tid];
        float a0[4] = {t0.x, t0.y, t0.z, t0.w};
        float a1[4] = {t1.x, t1.y, t1.z, t1.w};
#pragma unroll
        for (int k = 0; k < 4; ++k)
            if (a0[k] < v[k]) { v[k] = a0[k]; amin[k] = (short)r; }
#pragma unroll
        for (int k = 0; k < 4; ++k)
            if (a1[k] < v[k]) { v[k] = a1[k]; amin[k] = (short)(r + 1); }
    }
#pragma unroll
    for (int k = 0; k < 4; ++k) aminS[jc0 + k] = amin[k];
    __syncthreads();

    // ================= greedy assignment + lists (tid 0) ===================
    if (tid == 0) {
        for (int j = 0; j < N; ++j) {
            int i = aminS[j];
            if (!rowUsed[i]) { rowUsed[i] = 1; prow[j] = i; }
        }
        int nf = 0, na = 0;
        for (int i = 0; i < N; ++i)
            if (!rowUsed[i]) flist[nf++] = (short)i;
        for (int j = 0; j < N; ++j)
            if (prow[j] >= 0) alist[na++] = (short)j;
        s_nfree = nf; s_na = na;
    }
    __syncthreads();

    int pp = 0;

    // ================= JV reduction transfer ================================
    // Assigned pair (i, j1) has reduced cost 0 (column min). Set
    // u[i] = mu = min_{j != j1}(C[i][j] - v[j]);  v[j1] -= mu.  Exact fp32.
    {
        const int na = s_na;
        if (na > 0) LOADROW(c, prow[alist[0]]);
        for (int t = 0; t < na; ++t) {
            const int j1 = alist[t];
            float m = INF;
#pragma unroll
            for (int k = 0; k < 4; ++k) {
                float rc = c[k] - v[k];
                if (jc0 + k == j1) rc = INF;
                m = fminf(m, rc);
            }
            // overlap next row load with the reduction
            if (t + 1 < na) LOADROW(c, prow[alist[t + 1]]);

            unsigned mb = __reduce_min_sync(0xffffffffu, __float_as_uint(m));
            if (lane == 0) red1[pp][wrp] = mb;
            __syncthreads();
            const float mu = __uint_as_float(min(min(red1[pp][0], red1[pp][1]),
                                                 min(red1[pp][2], red1[pp][3])));
            if ((unsigned)(j1 - jc0) < 4u) v[j1 - jc0] -= mu;
            if (tid == 0) u[prow[j1]] = mu;
            pp ^= 1;
        }
        __syncthreads();
    }

    int head = 0, tail = s_nfree;
    const int lim = 2 * tail;
    int cnt = 0;

    // ================= augmenting row reduction (bounded JV ARR) ===========
    if (head < tail) LOADROW(c, flist[0]);
    while (head < tail && cnt < lim) {
        const int i = flist[head]; ++head; ++cnt;

        unsigned kk[4];
#pragma unroll
        for (int k = 0; k < 4; ++k) {
            float r0 = c[k] - v[k];
            kk[k] = ((__float_as_uint(r0) + 0x200u) & ~0x3FFu) | (unsigned)(jc0 + k);
        }
        unsigned m = min(min(kk[0], kk[1]), min(kk[2], kk[3]));
        m = __reduce_min_sync(0xffffffffu, m);
        if (lane == 0) red1[pp][wrp] = m;

        unsigned m2 = 0xFFFFFFFFu;
        __syncthreads();                                            // bar 1
        const unsigned g1 = min(min(red1[pp][0], red1[pp][1]),
                                min(red1[pp][2], red1[pp][3]));
        const int j1 = (int)(g1 & 0x3FFu);

#pragma unroll
        for (int k = 0; k < 4; ++k) m2 = min(m2, (kk[k] == g1) ? 0xFFFFFFFFu : kk[k]);
        m2 = __reduce_min_sync(0xffffffffu, m2);
        if (lane == 0) red2[pp][wrp] = m2;
        __syncthreads();                                            // bar 2
        const unsigned g2 = min(min(red2[pp][0], red2[pp][1]),
                                min(red2[pp][2], red2[pp][3]));
        const int j2 = (int)(g2 & 0x3FFu);
        const float u1 = __uint_as_float(g1 & ~0x3FFu);
        const float u2 = __uint_as_float(g2 & ~0x3FFu);

        int jsel = j1;
        if (u1 < u2) {
            if ((unsigned)(j1 - jc0) < 4u) v[j1 - jc0] -= (u2 - u1);
        } else if (prow[j1] >= 0) {
            jsel = j2;
        }
        if (tid == 0) {
            int iold = prow[jsel];
            prow[jsel] = i;
            u[i] = u2;
            if (iold >= 0) flist[tail] = (short)iold;
            s_iold = iold;
        }
        pp ^= 1;
        __syncthreads();                                            // bar 3
        if (s_iold >= 0) ++tail;
        if (head < tail && cnt < lim) LOADROW(c, flist[head]);
    }

    // ================= shortest augmenting paths ===========================
    if (head < tail) LOADROW(c, flist[head]);

    for (int idx = head; idx < tail; ++idx) {
        const int i = flist[idx];

        float    uinf[4];
        unsigned key[4];
#pragma unroll
        for (int k = 0; k < 4; ++k) { uinf[k] = 0.f; key[k] = 0xFFFFFFFFu; }

        float          base = -u[i];
        unsigned short j0s  = ROOTW;
        int   jpred1 = -1, jpred2 = -1;
        int   jfreeC;
        float dfinal;

        while (true) {
            // ---- relax my 4 columns ----
#pragma unroll
            for (int k = 0; k < 4; ++k) {
                float cur   = fmaxf((c[k] - v[k]) + base, uinf[k]);
                unsigned pc = ((__float_as_uint(cur) + 0x200u) & ~0x3FFu)
                              | (unsigned)(jc0 + k);
                if (pc < key[k]) { key[k] = pc; way[jc0 + k] = j0s; }
            }
            unsigned m = min(min(key[0], key[1]), min(key[2], key[3]));
            m = __reduce_min_sync(0xffffffffu, m);
            if (lane == 0) red1[pp][wrp] = m;
            __syncthreads();                                        // bar A
            const unsigned gmin = min(min(red1[pp][0], red1[pp][1]),
                                      min(red1[pp][2], red1[pp][3]));
            const int   j1 = (int)(gmin & 0x3FFu);
            const float dl = __uint_as_float(gmin & ~0x3FFu);

            const int i1 = prow[j1];
            if (i1 < 0) { jfreeC = j1; dfinal = dl; pp ^= 1; break; }

            if (tid == 0) dpop[j1] = dl;
#pragma unroll
            for (int k = 0; k < 4; ++k)
                if (key[k] == gmin) {
                    uinf[k] = INF;
                    key[k]  = 0x7F800000u | (unsigned)(jc0 + k);
                }

            // ---- pick row: 2-deep speculation, else demand load ----
            if (j1 == jpred1) {
#pragma unroll
                for (int k = 0; k < 4; ++k) c[k] = cS[k];
            } else if (j1 == jpred2) {
#pragma unroll
                for (int k = 0; k < 4; ++k) c[k] = cT[k];
            } else {
                LOADROW(c, i1);
            }

            // ---- runner-up + third-guess prediction (in the load shadow) --
            unsigned m2 = min(min(key[0], key[1]), min(key[2], key[3]));
            m2 = __reduce_min_sync(0xffffffffu, m2);
            if (lane == 0) red2[pp][wrp] = m2;
            __syncthreads();                                        // bar B
            {
                const unsigned r0 = red2[pp][0], r1 = red2[pp][1];
                const unsigned r2 = red2[pp][2], r3 = red2[pp][3];
                const unsigned lo01 = min(r0, r1), hi01 = max(r0, r1);
                const unsigned lo23 = min(r2, r3), hi23 = max(r2, r3);
                const unsigned g2 = min(lo01, lo23);
                const unsigned g3 = min(max(lo01, lo23), min(hi01, hi23));
                const int jp1 = (int)(g2 & 0x3FFu);
                const int jp2 = (int)(g3 & 0x3FFu);
                const int ip1 = prow[jp1];
                const int ip2 = prow[jp2];
                if (ip1 >= 0) { LOADROW(cS, ip1); jpred1 = jp1; } else jpred1 = -1;
                if (ip2 >= 0 && jp2 != jp1) { LOADROW(cT, ip2); jpred2 = jp2; }
                else jpred2 = -1;
            }

            base = dl - u[i1];
            j0s  = (unsigned short)j1;
            pp  ^= 1;
        }

        __syncthreads();              // dpop visible; all past break

        // prefetch next root row before serial tail
        if (idx + 1 < tail) LOADROW(c, flist[idx + 1]);

        // ---- one-shot dual updates ----
#pragma unroll
        for (int k = 0; k < 4; ++k) {
            if (uinf[k] > 0.f) {                  // col was popped
                int   j   = jc0 + k;
                float adj = dfinal - dpop[j];
                v[k]       -= adj;
                u[prow[j]] += adj;                // distinct rows: race-free
            }
        }
        if (tid == 0) u[i] += dfinal;
        __syncthreads();

        // ---- augment along alternating path (serial, tid 0) ----
        if (tid == 0) {
            int j = jfreeC;
            while (true) {
                int jpth = way[j];
                if (jpth == ROOTW) { prow[j] = i; break; }
                prow[j] = prow[jpth];
                j = jpth;
            }
        }
        __syncthreads();
    }

    // ---- matched-cost sum (double, deterministic order) ----
    double s = 0.0;
#pragma unroll
    for (int k = 0; k < 4; ++k) {
        int j = jc0 + k;
        s += (double)__ldg(&C[(size_t)prow[j] * N + j]);
    }
#pragma unroll
    for (int off = 16; off; off >>= 1)
        s += __shfl_down_sync(0xffffffffu, s, off);
    if (lane == 0) red_s[wrp] = s;
    __syncthreads();
    if (tid == 0)
        g_batch_sums[b] = ((red_s[0] + red_s[1]) + (red_s[2] + red_s[3]));
}

__global__ void finalize_kernel(float* __restrict__ out)
{
    const int lane = threadIdx.x;
    double s = (lane < B) ? g_batch_sums[lane] : 0.0;
#pragma unroll
    for (int off = 16; off; off >>= 1)
        s += __shfl_down_sync(0xffffffffu, s, off);
    if (lane == 0) out[0] = (float)(s / (double)(B * N));
}

extern "C" void kernel_launch(void* const* d_in, const int* in_sizes, int n_in,
                              void* d_out, int out_size)
{
    const float* D = (const float*)d_in[0];
    lap_kernel<<<B, NT>>>(D);
    finalize_kernel<<<1, 32>>>((float*)d_out);
}